// round 12
// baseline (speedup 1.0000x reference)
#include <cuda_runtime.h>
#include <math.h>

// Problem dims (fixed for this dataset entry)
#define BSZ   1024
#define HDIM  512
#define VOC   512
#define G4H   2048           // 4*H
#define KDIM  512

// ---------------- static device scratch ----------------
__device__ float g_Eproj[VOC * G4H];              // embedding @ W_ih^T + b_ih + b_hh
__device__ float g_gates[BSZ * G4H];              // h_prev @ W_hh^T
__device__ float g_c[BSZ * HDIM];
// Pre-split (hi,lo) tf32 operands, tile-contiguous.
// B layout: [n_tile(64 rows)][ch 16][row 64][18 float4]  (16 data + 2 pad)
__device__ float4 g_Bpk_wih[32 * 16 * 64 * 18];   // W_ih   (2048 rows)
__device__ float4 g_Bpk_wcat[40 * 16 * 64 * 18];  // [W_hh ; W_out] (2560 rows)
// A layout: [m_tile(128 rows)][ch 16][row 128][18 float4]
__device__ float4 g_Apk_h[8 * 16 * 128 * 18];     // h (1024 rows), rewritten per step
__device__ float4 g_Apk_emb[4 * 16 * 128 * 18];   // embedding (512 rows)
__device__ unsigned long long g_amax[2][BSZ];     // per-step-parity argmax keys

// ---------------- helpers (baseline sm_80+ PTX only) ----------------
__device__ __forceinline__ unsigned f2tf32(float x) {
    unsigned r; asm("cvt.rna.tf32.f32 %0, %1;" : "=r"(r) : "f"(x)); return r;
}
__device__ __forceinline__ void split4(float4 v, float4& h, float4& l) {
    h.x = __uint_as_float(f2tf32(v.x)); l.x = __uint_as_float(f2tf32(v.x - h.x));
    h.y = __uint_as_float(f2tf32(v.y)); l.y = __uint_as_float(f2tf32(v.y - h.y));
    h.z = __uint_as_float(f2tf32(v.z)); l.z = __uint_as_float(f2tf32(v.z - h.z));
    h.w = __uint_as_float(f2tf32(v.w)); l.w = __uint_as_float(f2tf32(v.w - h.w));
}
__device__ __forceinline__ void mma8(float* c, const unsigned* a, const unsigned* b) {
    asm volatile("mma.sync.aligned.m16n8k8.row.col.f32.tf32.tf32.f32 "
                 "{%0,%1,%2,%3}, {%4,%5,%6,%7}, {%8,%9}, {%0,%1,%2,%3};"
                 : "+f"(c[0]), "+f"(c[1]), "+f"(c[2]), "+f"(c[3])
                 : "r"(a[0]), "r"(a[1]), "r"(a[2]), "r"(a[3]), "r"(b[0]), "r"(b[1]));
}
__device__ __forceinline__ unsigned smem_u32(const void* p) {
    unsigned a;
    asm("{ .reg .u64 t; cvta.to.shared.u64 t, %1; cvt.u32.u64 %0, t; }" : "=r"(a) : "l"(p));
    return a;
}
#define CP16(dst, src) asm volatile("cp.async.cg.shared.global [%0], [%1], 16;" \
                                    :: "r"(dst), "l"(src) : "memory")
#define CP_COMMIT asm volatile("cp.async.commit_group;" ::: "memory")
#define CP_WAIT0  asm volatile("cp.async.wait_group 0;" ::: "memory")
#define CP_WAIT1  asm volatile("cp.async.wait_group 1;" ::: "memory")

__device__ __forceinline__ unsigned long long amax_key(float v, int col) {
    unsigned u = __float_as_uint(v);
    unsigned m = (u & 0x80000000u) ? ~u : (u | 0x80000000u);
    return ((unsigned long long)m << 32) | (unsigned)(511 - col);
}

// ---------------------------------------------------------------------------
// Pre-split operands: [nrows x 512] fp32 -> (hi,lo) packed tiles.
// tile_rows = 64 (B side) or 128 (A side); row = 16 data float4 + 2 pad.
// ---------------------------------------------------------------------------
__global__ void prepack(const float* __restrict__ src, float4* __restrict__ dst,
                        int nrows, int trshift)
{
    int i = blockIdx.x * blockDim.x + threadIdx.x;   // one per k-quad
    if (i >= nrows * 128) return;
    int n = i >> 7, q = i & 127;
    float4 v = reinterpret_cast<const float4*>(src)[(size_t)n * 128 + q];
    float4 h, l; split4(v, h, l);
    int tile = n >> trshift, r = n & ((1 << trshift) - 1), ch = q >> 3;
    int base4 = (((tile * 16 + ch) << trshift) + r) * 18 + (q & 7) * 2;
    dst[base4]     = make_float4(h.x, l.x, h.y, l.y);
    dst[base4 + 1] = make_float4(h.z, l.z, h.w, l.w);
}

__global__ void init_amax()
{
    int i = blockIdx.x * blockDim.x + threadIdx.x;
    if (i < BSZ) g_amax[1][i] = (1ULL << 32) | 511ULL;   // decodes to token 0 (SOS)
}

// ---------------------------------------------------------------------------
// TF32x3 HMMA GEMM, cp.async pipelined, both operands pre-split (hi,lo) packed.
// C[m,n] = sum_k A[m,k]*B[n,k]. Tile 128x64, K=512 in 16 chunks of 32,
// double-buffered smem. 8 warps as 4x2; warp tile 32x32.
// 3 mmas per frag-pair (AhBh + AhBl + AlBh) => fp32-faithful.
// Epilogue: n<nsplit -> C0(+b0a+b0b); else C1(+b1) + fused row-argmax atomics.
// smem buffer b at b*13824 floats: A packed [128][36 f2] = 9216 f, B packed [64][36 f2] = 4608 f.
// ---------------------------------------------------------------------------
#define BUF_FLOATS 13824
#define MM_SMEM    (2 * BUF_FLOATS * 4)   // 110592 bytes

__global__ __launch_bounds__(256, 2)
void mm_step(const float4* __restrict__ Apk, const float4* __restrict__ Bpk,
             float* __restrict__ C0, int ldc0,
             const float* __restrict__ b0a, const float* __restrict__ b0b,
             float* __restrict__ C1, int ldc1, const float* __restrict__ b1,
             int nsplit, unsigned long long* __restrict__ amax)
{
    extern __shared__ float sm[];
    const unsigned sbase = smem_u32(sm);
    const int tid  = threadIdx.x;
    const int wid  = tid >> 5, lane = tid & 31;
    const int g    = lane >> 2, t = lane & 3;
    const int m0   = blockIdx.y * 128, n0 = blockIdx.x * 64;
    const int nt   = blockIdx.x, mt = blockIdx.y;
    const int wrow = (wid >> 1) * 32;
    const int wcol = (wid & 1)  * 32;

    // async copy of chunk ch into buffer b: A 2304 + B 1152 contiguous 16B segs
    auto cpA = [&](int ch, int b) {
        unsigned sb = sbase + b * (BUF_FLOATS * 4);
        const float4* Asrc = Apk + (size_t)(mt * 16 + ch) * 2304;
        const float4* Bsrc = Bpk + (size_t)(nt * 16 + ch) * 1152;
#pragma unroll 1
        for (int i = tid; i < 3456; i += 256) {
            if (i < 2304) CP16(sb + i * 16, Asrc + i);
            else          CP16(sb + 36864 + (i - 2304) * 16, Bsrc + (i - 2304));
        }
    };

    float c[2][4][4];
#pragma unroll
    for (int mi = 0; mi < 2; mi++)
#pragma unroll
        for (int nj = 0; nj < 4; nj++)
#pragma unroll
            for (int q = 0; q < 4; q++) c[mi][nj][q] = 0.f;

    cpA(0, 0); CP_COMMIT;
    cpA(1, 1); CP_COMMIT;

    for (int ch = 0; ch < 16; ch++) {
        int b = ch & 1;
        if (ch < 15) { CP_WAIT1; } else { CP_WAIT0; }
        __syncthreads();

        const float2* pA = reinterpret_cast<const float2*>(sm + b * BUF_FLOATS);
        const float2* pB = reinterpret_cast<const float2*>(sm + b * BUF_FLOATS + 9216);

#pragma unroll
        for (int k8 = 0; k8 < 4; k8++) {
            int k0 = k8 * 8;
            unsigned ah[2][4], al[2][4];
#pragma unroll
            for (int mi = 0; mi < 2; mi++) {
                int ia = (wrow + 16 * mi + g) * 36 + k0 + t;
                float2 v0 = pA[ia],       v1 = pA[ia + 288];      // row, row+8 (k = t)
                float2 v2 = pA[ia + 4],   v3 = pA[ia + 292];      // row, row+8 (k = t+4)
                ah[mi][0] = __float_as_uint(v0.x); al[mi][0] = __float_as_uint(v0.y);
                ah[mi][1] = __float_as_uint(v1.x); al[mi][1] = __float_as_uint(v1.y);
                ah[mi][2] = __float_as_uint(v2.x); al[mi][2] = __float_as_uint(v2.y);
                ah[mi][3] = __float_as_uint(v3.x); al[mi][3] = __float_as_uint(v3.y);
            }
            unsigned bh[4][2], bl[4][2];
#pragma unroll
            for (int nj = 0; nj < 4; nj++) {
                int ib = (wcol + 8 * nj + g) * 36 + k0 + t;
                float2 v0 = pB[ib], v1 = pB[ib + 4];
                bh[nj][0] = __float_as_uint(v0.x); bl[nj][0] = __float_as_uint(v0.y);
                bh[nj][1] = __float_as_uint(v1.x); bl[nj][1] = __float_as_uint(v1.y);
            }
#pragma unroll
            for (int mi = 0; mi < 2; mi++)
#pragma unroll
                for (int nj = 0; nj < 4; nj++) {
                    mma8(c[mi][nj], ah[mi], bh[nj]);
                    mma8(c[mi][nj], ah[mi], bl[nj]);
                    mma8(c[mi][nj], al[mi], bh[nj]);
                }
        }

        if (ch < 14) { __syncthreads(); cpA(ch + 2, b); CP_COMMIT; }
    }

    // ---- epilogue: stage C in smem (stride 68), coalesced stores, fused argmax ----
    float* Cs = sm;   // buffer0 region free (last compute used buffer1)
#pragma unroll
    for (int mi = 0; mi < 2; mi++)
#pragma unroll
        for (int nj = 0; nj < 4; nj++) {
            int row = wrow + 16 * mi + g;
            int col = wcol + 8 * nj + 2 * t;
            *reinterpret_cast<float2*>(&Cs[row * 68 + col]) =
                make_float2(c[mi][nj][0], c[mi][nj][1]);
            *reinterpret_cast<float2*>(&Cs[(row + 8) * 68 + col]) =
                make_float2(c[mi][nj][2], c[mi][nj][3]);
        }
    __syncthreads();

    if (n0 + 64 <= nsplit) {
        for (int i = tid; i < 128 * 16; i += 256) {
            int rr = i >> 4, cq = (i & 15) << 2;
            float4 v = *reinterpret_cast<const float4*>(&Cs[rr * 68 + cq]);
            if (b0a) { float4 x = *reinterpret_cast<const float4*>(&b0a[n0 + cq]);
                       v.x += x.x; v.y += x.y; v.z += x.z; v.w += x.w; }
            if (b0b) { float4 x = *reinterpret_cast<const float4*>(&b0b[n0 + cq]);
                       v.x += x.x; v.y += x.y; v.z += x.z; v.w += x.w; }
            *reinterpret_cast<float4*>(&C0[(size_t)(m0 + rr) * ldc0 + n0 + cq]) = v;
        }
    } else {
        int nb = n0 - nsplit;
        for (int i = tid; i < 128 * 16; i += 256) {
            int rr = i >> 4, cq = (i & 15) << 2;
            float4 v = *reinterpret_cast<const float4*>(&Cs[rr * 68 + cq]);
            float4 x = *reinterpret_cast<const float4*>(&b1[nb + cq]);
            v.x += x.x; v.y += x.y; v.z += x.z; v.w += x.w;
            *reinterpret_cast<float4*>(&C1[(size_t)(m0 + rr) * ldc1 + nb + cq]) = v;

            int col = nb + cq;
            unsigned long long k = amax_key(v.x, col);
            unsigned long long k2 = amax_key(v.y, col + 1); if (k2 > k) k = k2;
            k2 = amax_key(v.z, col + 2); if (k2 > k) k = k2;
            k2 = amax_key(v.w, col + 3); if (k2 > k) k = k2;
#pragma unroll
            for (int off = 8; off; off >>= 1) {
                unsigned long long o = __shfl_down_sync(0xffffffffu, k, off, 16);
                if (o > k) k = o;
            }
            if ((tid & 15) == 0) atomicMax(&amax[m0 + rr], k);
        }
    }
}

// ---------------------------------------------------------------------------
// LSTM cell: gates = g_gates (h@W_hh^T) + Eproj[token]; PyTorch order i,f,g,o.
// Reads token from g_amax[par^1]; resets g_amax[par]. Writes h directly in
// (hi,lo)-packed A-tile layout for the next GEMM (bitwise-identical split).
// ---------------------------------------------------------------------------
__global__ void lstm_cell_kernel(int par)
{
    int idx = blockIdx.x * blockDim.x + threadIdx.x;
    if (idx >= BSZ * HDIM) return;
    int b  = idx >> 9;
    int hh = idx & (HDIM - 1);

    unsigned tok = 511u - (unsigned)(g_amax[par ^ 1][b] & 0xFFFFFFFFull);
    if (hh == 0) g_amax[par][b] = 0ull;

    const float* gr = g_gates + (size_t)b * G4H;
    const float* er = g_Eproj + (size_t)tok * G4H;

    float gi = gr[hh]          + er[hh];
    float gf = gr[HDIM + hh]   + er[HDIM + hh];
    float gg = gr[2*HDIM + hh] + er[2*HDIM + hh];
    float go = gr[3*HDIM + hh] + er[3*HDIM + hh];

    float si = 1.f / (1.f + expf(-gi));
    float sf = 1.f / (1.f + expf(-gf));
    float so = 1.f / (1.f + expf(-go));
    float tg = tanhf(gg);

    float cn = sf * g_c[idx] + si * tg;
    float hn = so * tanhf(cn);
    g_c[idx] = cn;

    // packed (hi,lo) write into A-tile layout
    float hi = __uint_as_float(f2tf32(hn));
    float lo = __uint_as_float(f2tf32(hn - hi));
    int mt = b >> 7, row = b & 127, ch = hh >> 5, kin = hh & 31;
    reinterpret_cast<float2*>(g_Apk_h)[((mt * 16 + ch) * 128 + row) * 36 + kin] =
        make_float2(hi, lo);
}

// ---------------------------------------------------------------------------
extern "C" void kernel_launch(void* const* d_in, const int* in_sizes, int n_in,
                              void* d_out, int out_size)
{
    const float *enc_h = nullptr, *enc_c = nullptr, *emb = nullptr,
                *W_ih = nullptr, *W_hh = nullptr, *b_ih = nullptr,
                *b_hh = nullptr, *W_out = nullptr, *b_out = nullptr;
    for (int i = 0; i < n_in; i++) {
        int s = in_sizes[i];
        const float* p = (const float*)d_in[i];
        if      (s == BSZ * HDIM) { if (!enc_h) enc_h = p; else if (!enc_c) enc_c = p; }
        else if (s == G4H * HDIM) { if (!W_ih)  W_ih  = p; else if (!W_hh)  W_hh  = p; }
        else if (s == VOC * HDIM) { if (!emb)   emb   = p; else if (!W_out) W_out = p; }
        else if (s == G4H)        { if (!b_ih)  b_ih  = p; else if (!b_hh)  b_hh  = p; }
        else if (s == VOC)        { if (!b_out) b_out = p; }
    }
    float* out = (float*)d_out;
    int T = out_size / (BSZ * VOC);   // 64

    float *pE, *pG, *pC; float4 *pBwih, *pBwcat, *pAh, *pAemb; unsigned long long* pAmax;
    cudaGetSymbolAddress((void**)&pE, g_Eproj);
    cudaGetSymbolAddress((void**)&pG, g_gates);
    cudaGetSymbolAddress((void**)&pC, g_c);
    cudaGetSymbolAddress((void**)&pBwih, g_Bpk_wih);
    cudaGetSymbolAddress((void**)&pBwcat, g_Bpk_wcat);
    cudaGetSymbolAddress((void**)&pAh, g_Apk_h);
    cudaGetSymbolAddress((void**)&pAemb, g_Apk_emb);
    cudaGetSymbolAddress((void**)&pAmax, g_amax);

    cudaFuncSetAttribute(mm_step, cudaFuncAttributeMaxDynamicSharedMemorySize, MM_SMEM);

    // Prologue: state init + operand pre-split + amax init
    cudaMemcpyAsync(pC, enc_c, (size_t)BSZ*HDIM*4, cudaMemcpyDeviceToDevice, 0);
    prepack<<<(2048*128)/256, 256>>>(W_ih,  pBwih,  2048, 6);                 // B tiles (64 rows)
    prepack<<<(2048*128)/256, 256>>>(W_hh,  pBwcat, 2048, 6);
    prepack<<<(512*128)/256,  256>>>(W_out, pBwcat + 32*16*64*18, 512, 6);
    prepack<<<(1024*128)/256, 256>>>(enc_h, pAh,    1024, 7);                 // A tiles (128 rows)
    prepack<<<(512*128)/256,  256>>>(emb,   pAemb,  512,  7);
    init_amax<<<4, 256>>>();

    // Eproj = embedding @ W_ih^T + (b_ih + b_hh)   [512 x 2048]
    mm_step<<<dim3(32, 4), 256, MM_SMEM>>>(
        pAemb, pBwih, pE, G4H, b_ih, b_hh, nullptr, 0, nullptr, G4H, nullptr);

    // hh_part(0) = enc_h @ W_hh^T                  [1024 x 2048]
    mm_step<<<dim3(32, 8), 256, MM_SMEM>>>(
        pAh, pBwcat, pG, G4H, nullptr, nullptr, nullptr, 0, nullptr, G4H, nullptr);

    for (int t = 0; t < T; t++) {
        lstm_cell_kernel<<<(BSZ*HDIM + 255)/256, 256>>>(t & 1);

        // Fused: [hh_part(t+1) | logits(t)+b_out] = h(t) @ [W_hh ; W_out]^T
        // Logits tiles also feed fused argmax atomics into g_amax[t&1].
        mm_step<<<dim3(40, 8), 256, MM_SMEM>>>(
            pAh, pBwcat, pG, G4H, nullptr, nullptr,
            out + (size_t)t * BSZ * VOC, VOC, b_out, G4H,
            pAmax + (size_t)(t & 1) * BSZ);
    }
}

// round 14
// speedup vs baseline: 1.1193x; 1.1193x over previous
#include <cuda_runtime.h>
#include <math.h>

// Problem dims (fixed for this dataset entry)
#define BSZ   1024
#define HDIM  512
#define VOC   512
#define G4H   2048           // 4*H
#define KDIM  512

// ---------------- static device scratch ----------------
__device__ float g_Eproj[VOC * G4H];              // embedding @ W_ih^T + b_ih + b_hh
__device__ float g_gates[BSZ * G4H];              // h_prev @ W_hh^T
__device__ float g_h[BSZ * HDIM];
__device__ float g_c[BSZ * HDIM];
// Pre-split (hi,lo) tf32 weights, tile-contiguous: [n_tile(64 rows)][ch 16][row 64][18 float4]
__device__ float4 g_Bpk_wih[32 * 16 * 64 * 18];   // W_ih   (2048 rows)
__device__ float4 g_Bpk_wcat[40 * 16 * 64 * 18];  // [W_hh ; W_out] (2560 rows)
__device__ unsigned long long g_amax[2][BSZ];     // per-step-parity argmax keys

// ---------------- helpers (baseline sm_80+ PTX only) ----------------
__device__ __forceinline__ unsigned f2tf32(float x) {
    unsigned r; asm("cvt.rna.tf32.f32 %0, %1;" : "=r"(r) : "f"(x)); return r;
}
__device__ __forceinline__ void split4(float4 v, float4& h, float4& l) {
    h.x = __uint_as_float(f2tf32(v.x)); l.x = __uint_as_float(f2tf32(v.x - h.x));
    h.y = __uint_as_float(f2tf32(v.y)); l.y = __uint_as_float(f2tf32(v.y - h.y));
    h.z = __uint_as_float(f2tf32(v.z)); l.z = __uint_as_float(f2tf32(v.z - h.z));
    h.w = __uint_as_float(f2tf32(v.w)); l.w = __uint_as_float(f2tf32(v.w - h.w));
}
__device__ __forceinline__ void mma8(float* c, const unsigned* a, const unsigned* b) {
    asm volatile("mma.sync.aligned.m16n8k8.row.col.f32.tf32.tf32.f32 "
                 "{%0,%1,%2,%3}, {%4,%5,%6,%7}, {%8,%9}, {%0,%1,%2,%3};"
                 : "+f"(c[0]), "+f"(c[1]), "+f"(c[2]), "+f"(c[3])
                 : "r"(a[0]), "r"(a[1]), "r"(a[2]), "r"(a[3]), "r"(b[0]), "r"(b[1]));
}
__device__ __forceinline__ unsigned smem_u32(const void* p) {
    unsigned a;
    asm("{ .reg .u64 t; cvta.to.shared.u64 t, %1; cvt.u32.u64 %0, t; }" : "=r"(a) : "l"(p));
    return a;
}
#define CP16(dst, src) asm volatile("cp.async.cg.shared.global [%0], [%1], 16;" \
                                    :: "r"(dst), "l"(src) : "memory")
#define CP_COMMIT asm volatile("cp.async.commit_group;" ::: "memory")
#define CP_WAIT0  asm volatile("cp.async.wait_group 0;" ::: "memory")
#define CP_WAIT1  asm volatile("cp.async.wait_group 1;" ::: "memory")

__device__ __forceinline__ unsigned long long amax_key(float v, int col) {
    unsigned u = __float_as_uint(v);
    unsigned m = (u & 0x80000000u) ? ~u : (u | 0x80000000u);
    return ((unsigned long long)m << 32) | (unsigned)(511 - col);
}

// ---------------------------------------------------------------------------
// Pre-split B weights: [nrows x 512] fp32 -> (hi,lo) packed 64-row tiles.
// ---------------------------------------------------------------------------
__global__ void prepack_B(const float* __restrict__ src, float4* __restrict__ dst, int nrows)
{
    int i = blockIdx.x * blockDim.x + threadIdx.x;   // one per k-quad
    if (i >= nrows * 128) return;
    int n = i >> 7, q = i & 127;
    float4 v = reinterpret_cast<const float4*>(src)[(size_t)n * 128 + q];
    float4 h, l; split4(v, h, l);
    int tile = n >> 6, r = n & 63, ch = q >> 3;
    int base4 = ((tile * 16 + ch) * 64 + r) * 18 + (q & 7) * 2;
    dst[base4]     = make_float4(h.x, l.x, h.y, l.y);
    dst[base4 + 1] = make_float4(h.z, l.z, h.w, l.w);
}

__global__ void init_amax()
{
    int i = blockIdx.x * blockDim.x + threadIdx.x;
    if (i < BSZ) g_amax[1][i] = (1ULL << 32) | 511ULL;   // decodes to token 0 (SOS)
}

// ---------------------------------------------------------------------------
// TF32x3 HMMA GEMM, cp.async pipelined.
// C[m,n] = sum_k A[m,k]*B[n,k]; A raw fp32 (K-contig rows), B pre-split packed.
// CTA tile 128x64, K=512 in 16 chunks of 32, double-buffered smem.
// 4 warps as 2x2; warp tile 64x32 (4 m-frags x 4 n-frags of m16n8k8).
// A hi-operand = raw fp32 (HW truncates to tf32); lo = x - (x & 0xFFFFE000).
// 3 mmas per frag-pair (AhBh + AhBl + AlBh) => fp32-faithful.
// Epilogue: n<nsplit -> C0(+b0a+b0b); else C1(+b1) + fused row-argmax atomics.
// smem buffer b at b*9216 floats: A raw [128][36] = 4608 f, B packed [64][36 f2] = 4608 f.
// ---------------------------------------------------------------------------
#define BUF_FLOATS 9216
#define MM_SMEM    (2 * BUF_FLOATS * 4)   // 73728 bytes

__global__ __launch_bounds__(128, 3)
void mm_step(const float* __restrict__ A, const float4* __restrict__ Bpk,
             float* __restrict__ C0, int ldc0,
             const float* __restrict__ b0a, const float* __restrict__ b0b,
             float* __restrict__ C1, int ldc1, const float* __restrict__ b1,
             int nsplit, unsigned long long* __restrict__ amax)
{
    extern __shared__ float sm[];
    const unsigned sbase = smem_u32(sm);
    const int tid  = threadIdx.x;
    const int wid  = tid >> 5, lane = tid & 31;
    const int g    = lane >> 2, t = lane & 3;
    const int m0   = blockIdx.y * 128, n0 = blockIdx.x * 64;
    const int nt   = blockIdx.x;
    const int wrow = (wid >> 1) * 64;
    const int wcol = (wid & 1)  * 32;

    const float* Ab = A + (size_t)m0 * KDIM;

    // async copy of chunk ch into buffer b: A 1024 + B 1152 16B segs
    auto cpA = [&](int ch, int b) {
        unsigned sb = sbase + b * (BUF_FLOATS * 4);
        const float*  Asrc = Ab + ch * 32;
        const float4* Bsrc = Bpk + (size_t)(nt * 16 + ch) * 1152;
#pragma unroll 1
        for (int i = tid; i < 2176; i += 128) {
            if (i < 1024) {
                int row = i >> 3, s = i & 7;
                CP16(sb + (row * 36 + s * 4) * 4, Asrc + (size_t)row * KDIM + s * 4);
            } else {
                int j = i - 1024;
                CP16(sb + 18432 + j * 16, Bsrc + j);
            }
        }
    };

    float c[4][4][4];
#pragma unroll
    for (int mi = 0; mi < 4; mi++)
#pragma unroll
        for (int nj = 0; nj < 4; nj++)
#pragma unroll
            for (int q = 0; q < 4; q++) c[mi][nj][q] = 0.f;

    cpA(0, 0); CP_COMMIT;
    cpA(1, 1); CP_COMMIT;

    for (int ch = 0; ch < 16; ch++) {
        int b = ch & 1;
        if (ch < 15) { CP_WAIT1; } else { CP_WAIT0; }
        __syncthreads();

        const float*  pA = sm + b * BUF_FLOATS;                                 // raw fp32
        const float2* pB = reinterpret_cast<const float2*>(sm + b * BUF_FLOATS + 4608);

#pragma unroll
        for (int k8 = 0; k8 < 4; k8++) {
            int k0 = k8 * 8;
            unsigned ah[4][4], al[4][4];
#pragma unroll
            for (int mi = 0; mi < 4; mi++) {
                int ia = (wrow + 16 * mi + g) * 36 + k0 + t;
                float x0 = pA[ia], x1 = pA[ia + 288], x2 = pA[ia + 4], x3 = pA[ia + 292];
                // hi = raw bits (HW reads top tf32 bits); lo = x - truncate(x)
                ah[mi][0] = __float_as_uint(x0);
                ah[mi][1] = __float_as_uint(x1);
                ah[mi][2] = __float_as_uint(x2);
                ah[mi][3] = __float_as_uint(x3);
                al[mi][0] = __float_as_uint(x0 - __uint_as_float(ah[mi][0] & 0xFFFFE000u));
                al[mi][1] = __float_as_uint(x1 - __uint_as_float(ah[mi][1] & 0xFFFFE000u));
                al[mi][2] = __float_as_uint(x2 - __uint_as_float(ah[mi][2] & 0xFFFFE000u));
                al[mi][3] = __float_as_uint(x3 - __uint_as_float(ah[mi][3] & 0xFFFFE000u));
            }
            unsigned bh[4][2], bl[4][2];
#pragma unroll
            for (int nj = 0; nj < 4; nj++) {
                int ib = (wcol + 8 * nj + g) * 36 + k0 + t;   // float2 units
                float2 v0 = pB[ib], v1 = pB[ib + 4];
                bh[nj][0] = __float_as_uint(v0.x); bl[nj][0] = __float_as_uint(v0.y);
                bh[nj][1] = __float_as_uint(v1.x); bl[nj][1] = __float_as_uint(v1.y);
            }
#pragma unroll
            for (int mi = 0; mi < 4; mi++)
#pragma unroll
                for (int nj = 0; nj < 4; nj++) {
                    mma8(c[mi][nj], ah[mi], bh[nj]);
                    mma8(c[mi][nj], ah[mi], bl[nj]);
                    mma8(c[mi][nj], al[mi], bh[nj]);
                }
        }

        if (ch < 14) { __syncthreads(); cpA(ch + 2, b); CP_COMMIT; }
    }

    // ---- epilogue: stage C in smem (stride 68), coalesced stores, fused argmax ----
    float* Cs = sm;   // buffer0 region free (last compute used buffer1)
#pragma unroll
    for (int mi = 0; mi < 4; mi++)
#pragma unroll
        for (int nj = 0; nj < 4; nj++) {
            int row = wrow + 16 * mi + g;
            int col = wcol + 8 * nj + 2 * t;
            *reinterpret_cast<float2*>(&Cs[row * 68 + col]) =
                make_float2(c[mi][nj][0], c[mi][nj][1]);
            *reinterpret_cast<float2*>(&Cs[(row + 8) * 68 + col]) =
                make_float2(c[mi][nj][2], c[mi][nj][3]);
        }
    __syncthreads();

    if (n0 + 64 <= nsplit) {
        for (int i = tid; i < 128 * 16; i += 128) {
            int rr = i >> 4, cq = (i & 15) << 2;
            float4 v = *reinterpret_cast<const float4*>(&Cs[rr * 68 + cq]);
            if (b0a) { float4 x = *reinterpret_cast<const float4*>(&b0a[n0 + cq]);
                       v.x += x.x; v.y += x.y; v.z += x.z; v.w += x.w; }
            if (b0b) { float4 x = *reinterpret_cast<const float4*>(&b0b[n0 + cq]);
                       v.x += x.x; v.y += x.y; v.z += x.z; v.w += x.w; }
            *reinterpret_cast<float4*>(&C0[(size_t)(m0 + rr) * ldc0 + n0 + cq]) = v;
        }
    } else {
        int nb = n0 - nsplit;
        for (int i = tid; i < 128 * 16; i += 128) {
            int rr = i >> 4, cq = (i & 15) << 2;
            float4 v = *reinterpret_cast<const float4*>(&Cs[rr * 68 + cq]);
            float4 x = *reinterpret_cast<const float4*>(&b1[nb + cq]);
            v.x += x.x; v.y += x.y; v.z += x.z; v.w += x.w;
            *reinterpret_cast<float4*>(&C1[(size_t)(m0 + rr) * ldc1 + nb + cq]) = v;

            // fused argmax partial: 4 cols per thread, 16-lane reduce, one atomic
            int col = nb + cq;
            unsigned long long k = amax_key(v.x, col);
            unsigned long long k2 = amax_key(v.y, col + 1); if (k2 > k) k = k2;
            k2 = amax_key(v.z, col + 2); if (k2 > k) k = k2;
            k2 = amax_key(v.w, col + 3); if (k2 > k) k = k2;
#pragma unroll
            for (int off = 8; off; off >>= 1) {
                unsigned long long o = __shfl_down_sync(0xffffffffu, k, off, 16);
                if (o > k) k = o;
            }
            if ((tid & 15) == 0) atomicMax(&amax[m0 + rr], k);
        }
    }
}

// ---------------------------------------------------------------------------
// LSTM cell: gates = g_gates (h@W_hh^T) + Eproj[token]; PyTorch order i,f,g,o.
// Reads token from g_amax[par^1]; resets g_amax[par] for this step's GEMM.
// ---------------------------------------------------------------------------
__global__ void lstm_cell_kernel(int par)
{
    int idx = blockIdx.x * blockDim.x + threadIdx.x;
    if (idx >= BSZ * HDIM) return;
    int b  = idx >> 9;
    int hh = idx & (HDIM - 1);

    unsigned tok = 511u - (unsigned)(g_amax[par ^ 1][b] & 0xFFFFFFFFull);
    if (hh == 0) g_amax[par][b] = 0ull;

    const float* gr = g_gates + (size_t)b * G4H;
    const float* er = g_Eproj + (size_t)tok * G4H;

    float gi = gr[hh]          + er[hh];
    float gf = gr[HDIM + hh]   + er[HDIM + hh];
    float gg = gr[2*HDIM + hh] + er[2*HDIM + hh];
    float go = gr[3*HDIM + hh] + er[3*HDIM + hh];

    float si = 1.f / (1.f + expf(-gi));
    float sf = 1.f / (1.f + expf(-gf));
    float so = 1.f / (1.f + expf(-go));
    float tg = tanhf(gg);

    float cn = sf * g_c[idx] + si * tg;
    float hn = so * tanhf(cn);
    g_c[idx] = cn;
    g_h[idx] = hn;
}

// ---------------------------------------------------------------------------
extern "C" void kernel_launch(void* const* d_in, const int* in_sizes, int n_in,
                              void* d_out, int out_size)
{
    const float *enc_h = nullptr, *enc_c = nullptr, *emb = nullptr,
                *W_ih = nullptr, *W_hh = nullptr, *b_ih = nullptr,
                *b_hh = nullptr, *W_out = nullptr, *b_out = nullptr;
    for (int i = 0; i < n_in; i++) {
        int s = in_sizes[i];
        const float* p = (const float*)d_in[i];
        if      (s == BSZ * HDIM) { if (!enc_h) enc_h = p; else if (!enc_c) enc_c = p; }
        else if (s == G4H * HDIM) { if (!W_ih)  W_ih  = p; else if (!W_hh)  W_hh  = p; }
        else if (s == VOC * HDIM) { if (!emb)   emb   = p; else if (!W_out) W_out = p; }
        else if (s == G4H)        { if (!b_ih)  b_ih  = p; else if (!b_hh)  b_hh  = p; }
        else if (s == VOC)        { if (!b_out) b_out = p; }
    }
    float* out = (float*)d_out;
    int T = out_size / (BSZ * VOC);   // 64

    float *pE, *pG, *pH, *pC; float4 *pBwih, *pBwcat; unsigned long long* pAmax;
    cudaGetSymbolAddress((void**)&pE, g_Eproj);
    cudaGetSymbolAddress((void**)&pG, g_gates);
    cudaGetSymbolAddress((void**)&pH, g_h);
    cudaGetSymbolAddress((void**)&pC, g_c);
    cudaGetSymbolAddress((void**)&pBwih, g_Bpk_wih);
    cudaGetSymbolAddress((void**)&pBwcat, g_Bpk_wcat);
    cudaGetSymbolAddress((void**)&pAmax, g_amax);

    cudaFuncSetAttribute(mm_step, cudaFuncAttributeMaxDynamicSharedMemorySize, MM_SMEM);

    // Prologue: state init + weight pre-split + amax init
    cudaMemcpyAsync(pH, enc_h, (size_t)BSZ*HDIM*4, cudaMemcpyDeviceToDevice, 0);
    cudaMemcpyAsync(pC, enc_c, (size_t)BSZ*HDIM*4, cudaMemcpyDeviceToDevice, 0);
    prepack_B<<<(2048*128)/256, 256>>>(W_ih,  pBwih,  2048);
    prepack_B<<<(2048*128)/256, 256>>>(W_hh,  pBwcat, 2048);
    prepack_B<<<(512*128)/256,  256>>>(W_out, pBwcat + 32*16*64*18, 512);
    init_amax<<<4, 256>>>();

    // Eproj = embedding @ W_ih^T + (b_ih + b_hh)   [512 x 2048]
    mm_step<<<dim3(32, 4), 128, MM_SMEM>>>(
        emb, pBwih, pE, G4H, b_ih, b_hh, nullptr, 0, nullptr, G4H, nullptr);

    // hh_part(0) = enc_h @ W_hh^T                  [1024 x 2048]
    mm_step<<<dim3(32, 8), 128, MM_SMEM>>>(
        enc_h, pBwcat, pG, G4H, nullptr, nullptr, nullptr, 0, nullptr, G4H, nullptr);

    for (int t = 0; t < T; t++) {
        lstm_cell_kernel<<<(BSZ*HDIM + 255)/256, 256>>>(t & 1);

        // Fused: [hh_part(t+1) | logits(t)+b_out] = h(t) @ [W_hh ; W_out]^T
        // Logits tiles also feed fused argmax atomics into g_amax[t&1].
        mm_step<<<dim3(40, 8), 128, MM_SMEM>>>(
            pH, pBwcat, pG, G4H, nullptr, nullptr,
            out + (size_t)t * BSZ * VOC, VOC, b_out, G4H,
            pAmax + (size_t)(t & 1) * BSZ);
    }
}